// round 9
// baseline (speedup 1.0000x reference)
#include <cuda_runtime.h>
#include <cuda_bf16.h>
#include <stdint.h>
#include <math.h>

#define S_LEN   2048
#define D_MODEL 2048
#define HD      64
#define NH      32
#define NKV     8
#define KVD     (NKV * HD)   // 512

// ---------------------------------------------------------------------------
// Scratch (__device__ globals; no allocation allowed)
// ---------------------------------------------------------------------------
__device__ float g_V[S_LEN * KVD];

__device__ __nv_bfloat16 g_xhi[S_LEN * D_MODEL], g_xlo[S_LEN * D_MODEL];
__device__ __nv_bfloat16 g_yhi[S_LEN * D_MODEL], g_ylo[S_LEN * D_MODEL];
__device__ __nv_bfloat16 g_qhi[S_LEN * D_MODEL], g_qlo[S_LEN * D_MODEL];
__device__ __nv_bfloat16 g_khi[S_LEN * KVD],     g_klo[S_LEN * KVD];
__device__ __nv_bfloat16 g_vthi[KVD * S_LEN],    g_vtlo[KVD * S_LEN];
__device__ __nv_bfloat16 g_wqT_hi[D_MODEL * D_MODEL], g_wqT_lo[D_MODEL * D_MODEL];
__device__ __nv_bfloat16 g_woT_hi[D_MODEL * D_MODEL], g_woT_lo[D_MODEL * D_MODEL];
__device__ __nv_bfloat16 g_wkT_hi[KVD * D_MODEL],     g_wkT_lo[KVD * D_MODEL];
__device__ __nv_bfloat16 g_wvT_hi[KVD * D_MODEL],     g_wvT_lo[KVD * D_MODEL];

// ---------------------------------------------------------------------------
// PTX helpers
// ---------------------------------------------------------------------------
__device__ __forceinline__ uint32_t smem_u32(const void* p) {
    uint32_t a;
    asm("{ .reg .u64 t; cvta.to.shared.u64 t, %1; cvt.u32.u64 %0, t; }" : "=r"(a) : "l"(p));
    return a;
}
__device__ __forceinline__ void mma16816(float* c, const uint32_t* a, const uint32_t* b) {
    asm volatile(
        "mma.sync.aligned.m16n8k16.row.col.f32.bf16.bf16.f32 "
        "{%0,%1,%2,%3}, {%4,%5,%6,%7}, {%8,%9}, {%0,%1,%2,%3};"
        : "+f"(c[0]), "+f"(c[1]), "+f"(c[2]), "+f"(c[3])
        : "r"(a[0]), "r"(a[1]), "r"(a[2]), "r"(a[3]), "r"(b[0]), "r"(b[1]));
}
__device__ __forceinline__ void ldsm_x4(uint32_t* r, uint32_t addr) {
    asm volatile("ldmatrix.sync.aligned.m8n8.x4.shared.b16 {%0,%1,%2,%3}, [%4];"
        : "=r"(r[0]), "=r"(r[1]), "=r"(r[2]), "=r"(r[3]) : "r"(addr));
}
#define CP_ASYNC16(dst, src) \
    asm volatile("cp.async.cg.shared.global [%0], [%1], 16;" :: "r"(dst), "l"(src))
#define CP_COMMIT() asm volatile("cp.async.commit_group;" ::: "memory")
#define CP_WAIT1()  asm volatile("cp.async.wait_group 1;" ::: "memory")
#define CP_WAIT0()  asm volatile("cp.async.wait_group 0;" ::: "memory")

__device__ __forceinline__ uint32_t pack_bf16x2(float lo, float hi) {
    __nv_bfloat162 t = __floats2bfloat162_rn(lo, hi);
    return *reinterpret_cast<uint32_t*>(&t);
}
__device__ __forceinline__ float2 unpack_bf16x2(uint32_t u) {
    __nv_bfloat162 t = *reinterpret_cast<__nv_bfloat162*>(&u);
    return make_float2(__bfloat162float(t.x), __bfloat162float(t.y));
}
__device__ __forceinline__ void store_split(__nv_bfloat16* Hi, __nv_bfloat16* Lo,
                                            size_t idx, float v0, float v1) {
    uint32_t h = pack_bf16x2(v0, v1);
    float2 f = unpack_bf16x2(h);
    uint32_t l = pack_bf16x2(v0 - f.x, v1 - f.y);
    *(uint32_t*)&Hi[idx] = h;
    *(uint32_t*)&Lo[idx] = l;
}

// ---------------------------------------------------------------------------
// Split fp32 -> bf16 hi + lo
// ---------------------------------------------------------------------------
__global__ void split_kernel(const float* __restrict__ src,
                             __nv_bfloat16* __restrict__ hi,
                             __nv_bfloat16* __restrict__ lo, int n, float scale) {
    int i = blockIdx.x * 256 + threadIdx.x;
    if (i >= n) return;
    float v = src[i] * scale;
    __nv_bfloat16 h = __float2bfloat16(v);
    hi[i] = h;
    lo[i] = __float2bfloat16(v - __bfloat162float(h));
}

// ---------------------------------------------------------------------------
// Transpose + split: W[rows][Nd] fp32 -> WT[Nd][rows] bf16 hi/lo
// ---------------------------------------------------------------------------
__global__ void transpose_split_kernel(const float* __restrict__ W,
                                       __nv_bfloat16* __restrict__ Thi,
                                       __nv_bfloat16* __restrict__ Tlo,
                                       int Kd, int Nd) {
    __shared__ float t[32][33];
    int bx = blockIdx.x * 32;
    int by = blockIdx.y * 32;
    int tx = threadIdx.x, ty = threadIdx.y;
#pragma unroll
    for (int j = 0; j < 32; j += 8)
        t[ty + j][tx] = W[(size_t)(by + ty + j) * Nd + bx + tx];
    __syncthreads();
#pragma unroll
    for (int j = 0; j < 32; j += 8) {
        int n = bx + ty + j, k = by + tx;
        float v = t[tx][ty + j];
        __nv_bfloat16 h = __float2bfloat16(v);
        Thi[(size_t)n * Kd + k] = h;
        Tlo[(size_t)n * Kd + k] = __float2bfloat16(v - __bfloat162float(h));
    }
}

// ---------------------------------------------------------------------------
// Pipelined warp-MMA GEMM (ldmatrix), split-bf16 x3, pass-major MMA order.
// Modes: 0 fp32 | 1 scale+bf16split | 2 RoPE+bf16split | 3 RoPE+fp32
// ---------------------------------------------------------------------------
#define SA  40
#define GTB (128 * SA * 2)          // 10240
#define GEMM_SMEM (2 * 4 * GTB)     // 81920

__global__ __launch_bounds__(256) void gemm_mma_x3(
    const __nv_bfloat16* __restrict__ Ahi, const __nv_bfloat16* __restrict__ Alo,
    const __nv_bfloat16* __restrict__ Bhi, const __nv_bfloat16* __restrict__ Blo,
    float* __restrict__ Cf, __nv_bfloat16* __restrict__ Chi, __nv_bfloat16* __restrict__ Clo,
    const float* __restrict__ cosv, const float* __restrict__ sinv,
    int N, int Kd, int mode, float scale) {

    extern __shared__ char dsm[];
    uint32_t sb = smem_u32(dsm);

    const int tid  = threadIdx.x;
    const int lane = tid & 31;
    const int wid  = tid >> 5;
    const int wm   = (wid >> 1) * 32;
    const int wn   = (wid & 1) * 64;
    const int bm   = blockIdx.y * 128;
    const int bn   = blockIdx.x * 128;
    const int lrow = tid >> 2;
    const int lcb  = (tid & 3) * 16;
    const int grp  = lane >> 2;
    const int qd   = (lane & 3) * 2;

    const int arow_l = (lane & 7) + (((lane >> 3) & 1) << 3);
    const int acol_l = (lane >> 4) << 3;
    const int brow_l = (lane & 7) + ((lane >> 4) << 3);
    const int bcol_l = ((lane >> 3) & 1) << 3;

    const int nIter = Kd / 32;

    auto issue = [&](int it, int stage) {
        const size_t kb = (size_t)it * 64;
        uint32_t base = sb + stage * (4 * GTB);
#pragma unroll
        for (int rr = 0; rr < 2; rr++) {
            int row = lrow + rr * 64;
            uint32_t so = row * (SA * 2) + lcb;
            const char* g = (const char*)Ahi + ((size_t)(bm + row) * Kd) * 2 + kb + lcb;
            CP_ASYNC16(base + so, g);
            g = (const char*)Alo + ((size_t)(bm + row) * Kd) * 2 + kb + lcb;
            CP_ASYNC16(base + GTB + so, g);
            g = (const char*)Bhi + ((size_t)(bn + row) * Kd) * 2 + kb + lcb;
            CP_ASYNC16(base + 2 * GTB + so, g);
            g = (const char*)Blo + ((size_t)(bn + row) * Kd) * 2 + kb + lcb;
            CP_ASYNC16(base + 3 * GTB + so, g);
        }
        CP_COMMIT();
    };

    float acc[2][8][4];
#pragma unroll
    for (int i = 0; i < 2; i++)
#pragma unroll
        for (int j = 0; j < 8; j++)
#pragma unroll
            for (int k = 0; k < 4; k++) acc[i][j][k] = 0.f;

    issue(0, 0);
    if (nIter > 1) issue(1, 1);

    for (int it = 0; it < nIter; it++) {
        if (it + 1 < nIter) { CP_WAIT1(); } else { CP_WAIT0(); }
        __syncthreads();

        uint32_t buf = sb + (it & 1) * (4 * GTB);

#pragma unroll
        for (int ks = 0; ks < 2; ks++) {
            const int kc = ks * 16;
            uint32_t ah[2][4], al[2][4];
            uint32_t a0 = buf + ((wm + arow_l) * SA + kc + acol_l) * 2;
            ldsm_x4(ah[0], a0);
            ldsm_x4(ah[1], a0 + 16 * SA * 2);
            ldsm_x4(al[0], a0 + GTB);
            ldsm_x4(al[1], a0 + GTB + 16 * SA * 2);

            uint32_t bhf[16], blf[16];
            uint32_t b0 = buf + 2 * GTB + ((wn + brow_l) * SA + kc + bcol_l) * 2;
#pragma unroll
            for (int p = 0; p < 4; p++) {
                ldsm_x4(&bhf[p * 4], b0 + p * 16 * SA * 2);
                ldsm_x4(&blf[p * 4], b0 + GTB + p * 16 * SA * 2);
            }
            // Pass-major: 16 independent accumulators between same-acc reuse
#pragma unroll
            for (int mt = 0; mt < 2; mt++)
#pragma unroll
                for (int nt = 0; nt < 8; nt++)
                    mma16816(acc[mt][nt], ah[mt], &bhf[nt * 2]);
#pragma unroll
            for (int mt = 0; mt < 2; mt++)
#pragma unroll
                for (int nt = 0; nt < 8; nt++)
                    mma16816(acc[mt][nt], ah[mt], &blf[nt * 2]);
#pragma unroll
            for (int mt = 0; mt < 2; mt++)
#pragma unroll
                for (int nt = 0; nt < 8; nt++)
                    mma16816(acc[mt][nt], al[mt], &bhf[nt * 2]);
        }
        __syncthreads();
        if (it + 2 < nIter) issue(it + 2, it & 1);
    }

    // ---- epilogue ----
#pragma unroll
    for (int mt = 0; mt < 2; mt++) {
        int r = bm + wm + mt * 16 + grp;
#pragma unroll
        for (int nt = 0; nt < 8; nt++) {
            int c = bn + wn + nt * 8 + qd;
            float a0 = acc[mt][nt][0], a1 = acc[mt][nt][1];
            float a2 = acc[mt][nt][2], a3 = acc[mt][nt][3];
            size_t i0 = (size_t)r * N + c;
            size_t i1 = (size_t)(r + 8) * N + c;
            if (mode == 0) {
                *(float2*)&Cf[i0] = make_float2(a0, a1);
                *(float2*)&Cf[i1] = make_float2(a2, a3);
            } else if (mode == 1) {
                store_split(Chi, Clo, i0, a0 * scale, a1 * scale);
                store_split(Chi, Clo, i1, a2 * scale, a3 * scale);
            } else {
                int d2 = (c & 63) >> 1;
                float c0 = cosv[r * 32 + d2],       s0 = sinv[r * 32 + d2];
                float c1 = cosv[(r + 8) * 32 + d2], s1 = sinv[(r + 8) * 32 + d2];
                float o0 = a0 * c0 - a1 * s0, o1 = a0 * s0 + a1 * c0;
                float o2 = a2 * c1 - a3 * s1, o3 = a2 * s1 + a3 * c1;
                if (mode == 3) {
                    *(float2*)&Cf[i0] = make_float2(o0, o1);
                    *(float2*)&Cf[i1] = make_float2(o2, o3);
                } else {
                    store_split(Chi, Clo, i0, o0, o1);
                    store_split(Chi, Clo, i1, o2, o3);
                }
            }
        }
    }
}

// ---------------------------------------------------------------------------
// Pipelined MMA flash attention (ldmatrix), causal GQA, split-bf16 x3,
// pass-major MMA order. Grid (S/128, NH), 256 threads.
// ---------------------------------------------------------------------------
#define AST 72
#define ATB (64 * AST * 2)          // 9216
#define ATTN_SMEM (2 * 4 * ATB)     // 73728

__global__ __launch_bounds__(256) void attn_mma(
    const __nv_bfloat16* __restrict__ Qhi, const __nv_bfloat16* __restrict__ Qlo,
    const __nv_bfloat16* __restrict__ Khi, const __nv_bfloat16* __restrict__ Klo,
    const __nv_bfloat16* __restrict__ VThi, const __nv_bfloat16* __restrict__ VTlo,
    __nv_bfloat16* __restrict__ Yhi, __nv_bfloat16* __restrict__ Ylo) {

    extern __shared__ char dsm[];
    uint32_t sb = smem_u32(dsm);

    const int h    = blockIdx.y;
    const int kvh  = h >> 2;
    const int q0   = (gridDim.x - 1 - blockIdx.x) * 128;   // long tiles first
    const int tid  = threadIdx.x;
    const int lane = tid & 31;
    const int w    = tid >> 5;
    const int grp  = lane >> 2;
    const int qd   = (lane & 3) * 2;
    const int r0   = q0 + w * 16 + grp;

    const int brow_l = (lane & 7) + ((lane >> 4) << 3);
    const int bcol_l = ((lane >> 3) & 1) << 3;

    const int nChunks = (q0 >> 6) + 2;

    auto issueA = [&](int ci, int stage) {
        const int j0 = ci << 6;
        uint32_t base = sb + stage * (4 * ATB);
#pragma unroll
        for (int i = 0; i < 2; i++) {
            int c   = tid + i * 256;
            int row = c >> 3;
            int cb  = (c & 7) * 16;
            uint32_t so = row * (AST * 2) + cb;
            const char* g = (const char*)Khi + ((size_t)(j0 + row) * KVD + kvh * HD) * 2 + cb;
            CP_ASYNC16(base + so, g);
            g = (const char*)Klo + ((size_t)(j0 + row) * KVD + kvh * HD) * 2 + cb;
            CP_ASYNC16(base + ATB + so, g);
            g = (const char*)VThi + ((size_t)(kvh * HD + row) * S_LEN + j0) * 2 + cb;
            CP_ASYNC16(base + 2 * ATB + so, g);
            g = (const char*)VTlo + ((size_t)(kvh * HD + row) * S_LEN + j0) * 2 + cb;
            CP_ASYNC16(base + 3 * ATB + so, g);
        }
        CP_COMMIT();
    };

    // Q fragments, loaded once
    uint32_t qh[4][4], ql[4][4];
#pragma unroll
    for (int jk = 0; jk < 4; jk++) {
        size_t c0 = (size_t)r0 * D_MODEL + h * HD + jk * 16 + qd;
        size_t c1 = (size_t)(r0 + 8) * D_MODEL + h * HD + jk * 16 + qd;
        qh[jk][0] = *(const uint32_t*)&Qhi[c0];
        qh[jk][1] = *(const uint32_t*)&Qhi[c1];
        qh[jk][2] = *(const uint32_t*)&Qhi[c0 + 8];
        qh[jk][3] = *(const uint32_t*)&Qhi[c1 + 8];
        ql[jk][0] = *(const uint32_t*)&Qlo[c0];
        ql[jk][1] = *(const uint32_t*)&Qlo[c1];
        ql[jk][2] = *(const uint32_t*)&Qlo[c0 + 8];
        ql[jk][3] = *(const uint32_t*)&Qlo[c1 + 8];
    }

    float o[8][4];
#pragma unroll
    for (int nt = 0; nt < 8; nt++)
#pragma unroll
        for (int i = 0; i < 4; i++) o[nt][i] = 0.f;

    float m0 = -1e30f, m1 = -1e30f, l0 = 0.f, l1 = 0.f;

    issueA(0, 0);
    if (nChunks > 1) issueA(1, 1);

    for (int ci = 0; ci < nChunks; ci++) {
        const int j0 = ci << 6;
        if (ci + 1 < nChunks) { CP_WAIT1(); } else { CP_WAIT0(); }
        __syncthreads();

        uint32_t buf = sb + (ci & 1) * (4 * ATB);

        // S = Q K^T (x3), pass-major
        float s[8][4];
#pragma unroll
        for (int nt = 0; nt < 8; nt++)
#pragma unroll
            for (int i = 0; i < 4; i++) s[nt][i] = 0.f;

#pragma unroll
        for (int jk = 0; jk < 4; jk++) {
            uint32_t bhf[16], blf[16];
            uint32_t b0 = buf + (brow_l * AST + jk * 16 + bcol_l) * 2;
#pragma unroll
            for (int p = 0; p < 4; p++) {
                ldsm_x4(&bhf[p * 4], b0 + p * 16 * AST * 2);
                ldsm_x4(&blf[p * 4], b0 + ATB + p * 16 * AST * 2);
            }
#pragma unroll
            for (int nt = 0; nt < 8; nt++)
                mma16816(s[nt], qh[jk], &bhf[nt * 2]);
#pragma unroll
            for (int nt = 0; nt < 8; nt++)
                mma16816(s[nt], qh[jk], &blf[nt * 2]);
#pragma unroll
            for (int nt = 0; nt < 8; nt++)
                mma16816(s[nt], ql[jk], &bhf[nt * 2]);
        }

        if (ci >= nChunks - 2) {
#pragma unroll
            for (int nt = 0; nt < 8; nt++) {
                int col = j0 + nt * 8 + qd;
                if (col     > r0)     s[nt][0] = -1e30f;
                if (col + 1 > r0)     s[nt][1] = -1e30f;
                if (col     > r0 + 8) s[nt][2] = -1e30f;
                if (col + 1 > r0 + 8) s[nt][3] = -1e30f;
            }
        }

        float mx0 = -1e30f, mx1 = -1e30f;
#pragma unroll
        for (int nt = 0; nt < 8; nt++) {
            mx0 = fmaxf(mx0, fmaxf(s[nt][0], s[nt][1]));
            mx1 = fmaxf(mx1, fmaxf(s[nt][2], s[nt][3]));
        }
        mx0 = fmaxf(mx0, __shfl_xor_sync(0xffffffffu, mx0, 1));
        mx0 = fmaxf(mx0, __shfl_xor_sync(0xffffffffu, mx0, 2));
        mx1 = fmaxf(mx1, __shfl_xor_sync(0xffffffffu, mx1, 1));
        mx1 = fmaxf(mx1, __shfl_xor_sync(0xffffffffu, mx1, 2));

        float nm0 = fmaxf(m0, mx0), nm1 = fmaxf(m1, mx1);
        float corr0 = __expf(m0 - nm0), corr1 = __expf(m1 - nm1);

        uint32_t ph[4][4], pl[4][4];
        float sum0 = 0.f, sum1 = 0.f;
#pragma unroll
        for (int nt = 0; nt < 8; nt++) {
            float p0 = __expf(s[nt][0] - nm0), p1 = __expf(s[nt][1] - nm0);
            float p2 = __expf(s[nt][2] - nm1), p3 = __expf(s[nt][3] - nm1);
            sum0 += p0 + p1;
            sum1 += p2 + p3;
            uint32_t h01 = pack_bf16x2(p0, p1);
            uint32_t h23 = pack_bf16x2(p2, p3);
            float2 f01 = unpack_bf16x2(h01);
            float2 f23 = unpack_bf16x2(h23);
            uint32_t lo01 = pack_bf16x2(p0 - f01.x, p1 - f01.y);
            uint32_t lo23 = pack_bf16x2(p2 - f23.x, p3 - f23.y);
            int jk2 = nt >> 1, hf = (nt & 1) * 2;
            ph[jk2][hf]     = h01;
            ph[jk2][hf + 1] = h23;
            pl[jk2][hf]     = lo01;
            pl[jk2][hf + 1] = lo23;
        }
        sum0 += __shfl_xor_sync(0xffffffffu, sum0, 1);
        sum0 += __shfl_xor_sync(0xffffffffu, sum0, 2);
        sum1 += __shfl_xor_sync(0xffffffffu, sum1, 1);
        sum1 += __shfl_xor_sync(0xffffffffu, sum1, 2);
        l0 = l0 * corr0 + sum0;
        l1 = l1 * corr1 + sum1;
        m0 = nm0; m1 = nm1;

#pragma unroll
        for (int nt = 0; nt < 8; nt++) {
            o[nt][0] *= corr0; o[nt][1] *= corr0;
            o[nt][2] *= corr1; o[nt][3] *= corr1;
        }

        // O += P V (x3), pass-major
#pragma unroll
        for (int jk = 0; jk < 4; jk++) {
            uint32_t bhf[16], blf[16];
            uint32_t b0 = buf + 2 * ATB + (brow_l * AST + jk * 16 + bcol_l) * 2;
#pragma unroll
            for (int p = 0; p < 4; p++) {
                ldsm_x4(&bhf[p * 4], b0 + p * 16 * AST * 2);
                ldsm_x4(&blf[p * 4], b0 + ATB + p * 16 * AST * 2);
            }
#pragma unroll
            for (int nt = 0; nt < 8; nt++)
                mma16816(o[nt], ph[jk], &bhf[nt * 2]);
#pragma unroll
            for (int nt = 0; nt < 8; nt++)
                mma16816(o[nt], ph[jk], &blf[nt * 2]);
#pragma unroll
            for (int nt = 0; nt < 8; nt++)
                mma16816(o[nt], pl[jk], &bhf[nt * 2]);
        }

        __syncthreads();
        if (ci + 2 < nChunks) issueA(ci + 2, ci & 1);
    }

    float il0 = 1.f / l0, il1 = 1.f / l1;
#pragma unroll
    for (int nt = 0; nt < 8; nt++) {
        size_t c0 = (size_t)r0 * D_MODEL + h * HD + nt * 8 + qd;
        size_t c1 = (size_t)(r0 + 8) * D_MODEL + h * HD + nt * 8 + qd;
        store_split(Yhi, Ylo, c0, o[nt][0] * il0, o[nt][1] * il0);
        store_split(Yhi, Ylo, c1, o[nt][2] * il1, o[nt][3] * il1);
    }
}

// ---------------------------------------------------------------------------
extern "C" void kernel_launch(void* const* d_in, const int* in_sizes, int n_in,
                              void* d_out, int out_size) {
    const float* x    = (const float*)d_in[0];
    const float* tcos = (const float*)d_in[1];
    const float* tsin = (const float*)d_in[2];
    const float* wq   = (const float*)d_in[3];
    const float* wk   = (const float*)d_in[4];
    const float* wv   = (const float*)d_in[5];
    const float* wo   = (const float*)d_in[6];
    float* out = (float*)d_out;

    float* V;
    cudaGetSymbolAddress((void**)&V, g_V);

    __nv_bfloat16 *xhi, *xlo, *yhi, *ylo, *qhi, *qlo, *khi, *klo, *vthi, *vtlo;
    __nv_bfloat16 *wqThi, *wqTlo, *wkThi, *wkTlo, *wvThi, *wvTlo, *woThi, *woTlo;
    cudaGetSymbolAddress((void**)&xhi, g_xhi);   cudaGetSymbolAddress((void**)&xlo, g_xlo);
    cudaGetSymbolAddress((void**)&yhi, g_yhi);   cudaGetSymbolAddress((void**)&ylo, g_ylo);
    cudaGetSymbolAddress((void**)&qhi, g_qhi);   cudaGetSymbolAddress((void**)&qlo, g_qlo);
    cudaGetSymbolAddress((void**)&khi, g_khi);   cudaGetSymbolAddress((void**)&klo, g_klo);
    cudaGetSymbolAddress((void**)&vthi, g_vthi); cudaGetSymbolAddress((void**)&vtlo, g_vtlo);
    cudaGetSymbolAddress((void**)&wqThi, g_wqT_hi); cudaGetSymbolAddress((void**)&wqTlo, g_wqT_lo);
    cudaGetSymbolAddress((void**)&wkThi, g_wkT_hi); cudaGetSymbolAddress((void**)&wkTlo, g_wkT_lo);
    cudaGetSymbolAddress((void**)&wvThi, g_wvT_hi); cudaGetSymbolAddress((void**)&wvTlo, g_wvT_lo);
    cudaGetSymbolAddress((void**)&woThi, g_woT_hi); cudaGetSymbolAddress((void**)&woTlo, g_woT_lo);

    cudaFuncSetAttribute(gemm_mma_x3, cudaFuncAttributeMaxDynamicSharedMemorySize, GEMM_SMEM);
    cudaFuncSetAttribute(attn_mma,    cudaFuncAttributeMaxDynamicSharedMemorySize, ATTN_SMEM);

    const int nx = S_LEN * D_MODEL;

    // Split x into bf16 hi/lo
    split_kernel<<<(nx + 255) / 256, 256>>>(x, xhi, xlo, nx, 1.0f);

    // Transpose+split weights: W[K][N] -> WT[N][K]
    transpose_split_kernel<<<dim3(D_MODEL / 32, D_MODEL / 32), dim3(32, 8)>>>(wq, wqThi, wqTlo, D_MODEL, D_MODEL);
    transpose_split_kernel<<<dim3(KVD / 32,     D_MODEL / 32), dim3(32, 8)>>>(wk, wkThi, wkTlo, D_MODEL, KVD);
    transpose_split_kernel<<<dim3(KVD / 32,     D_MODEL / 32), dim3(32, 8)>>>(wv, wvThi, wvTlo, D_MODEL, KVD);
    transpose_split_kernel<<<dim3(D_MODEL / 32, D_MODEL / 32), dim3(32, 8)>>>(wo, woThi, woTlo, D_MODEL, D_MODEL);

    // Q projection: fused scale + bf16 split epilogue
    gemm_mma_x3<<<dim3(D_MODEL / 128, S_LEN / 128), 256, GEMM_SMEM>>>(
        xhi, xlo, wqThi, wqTlo, nullptr, qhi, qlo, nullptr, nullptr,
        D_MODEL, D_MODEL, 1, 0.125f);
    // K projection: fused RoPE + bf16 split epilogue
    gemm_mma_x3<<<dim3(KVD / 128, S_LEN / 128), 256, GEMM_SMEM>>>(
        xhi, xlo, wkThi, wkTlo, nullptr, khi, klo, tcos, tsin,
        KVD, D_MODEL, 2, 1.0f);
    // V projection: fused RoPE, fp32 out (then transposed)
    gemm_mma_x3<<<dim3(KVD / 128, S_LEN / 128), 256, GEMM_SMEM>>>(
        xhi, xlo, wvThi, wvTlo, V, nullptr, nullptr, tcos, tsin,
        KVD, D_MODEL, 3, 1.0f);

    // V transpose+split for attention ([dim][seq])
    transpose_split_kernel<<<dim3(KVD / 32, S_LEN / 32), dim3(32, 8)>>>(V, vthi, vtlo, S_LEN, KVD);

    // MMA flash attention -> Yhi/Ylo
    attn_mma<<<dim3(S_LEN / 128, NH), 256, ATTN_SMEM>>>(qhi, qlo, khi, klo, vthi, vtlo, yhi, ylo);

    // Output projection (fp32 out)
    gemm_mma_x3<<<dim3(D_MODEL / 128, S_LEN / 128), 256, GEMM_SMEM>>>(
        yhi, ylo, woThi, woTlo, out, nullptr, nullptr, nullptr, nullptr,
        D_MODEL, D_MODEL, 0, 1.0f);
}

// round 10
// speedup vs baseline: 2.3986x; 2.3986x over previous
#include <cuda_runtime.h>
#include <cuda_fp16.h>
#include <stdint.h>
#include <math.h>

#define S_LEN   2048
#define D_MODEL 2048
#define HD      64
#define NH      32
#define NKV     8
#define KVD     (NKV * HD)   // 512

// ---------------------------------------------------------------------------
// Scratch (__device__ globals; no allocation allowed)
// ---------------------------------------------------------------------------
__device__ float  g_V[S_LEN * KVD];
__device__ __half g_xh[S_LEN * D_MODEL];
__device__ __half g_yh[S_LEN * D_MODEL];
__device__ __half g_qh[S_LEN * D_MODEL];
__device__ __half g_kh[S_LEN * KVD];
__device__ __half g_vth[KVD * S_LEN];
__device__ __half g_wqT[D_MODEL * D_MODEL];
__device__ __half g_woT[D_MODEL * D_MODEL];
__device__ __half g_wkT[KVD * D_MODEL];
__device__ __half g_wvT[KVD * D_MODEL];

// ---------------------------------------------------------------------------
// PTX helpers
// ---------------------------------------------------------------------------
__device__ __forceinline__ uint32_t smem_u32(const void* p) {
    uint32_t a;
    asm("{ .reg .u64 t; cvta.to.shared.u64 t, %1; cvt.u32.u64 %0, t; }" : "=r"(a) : "l"(p));
    return a;
}
__device__ __forceinline__ void mma16816(float* c, const uint32_t* a, const uint32_t* b) {
    asm volatile(
        "mma.sync.aligned.m16n8k16.row.col.f32.f16.f16.f32 "
        "{%0,%1,%2,%3}, {%4,%5,%6,%7}, {%8,%9}, {%0,%1,%2,%3};"
        : "+f"(c[0]), "+f"(c[1]), "+f"(c[2]), "+f"(c[3])
        : "r"(a[0]), "r"(a[1]), "r"(a[2]), "r"(a[3]), "r"(b[0]), "r"(b[1]));
}
__device__ __forceinline__ void ldsm_x4(uint32_t* r, uint32_t addr) {
    asm volatile("ldmatrix.sync.aligned.m8n8.x4.shared.b16 {%0,%1,%2,%3}, [%4];"
        : "=r"(r[0]), "=r"(r[1]), "=r"(r[2]), "=r"(r[3]) : "r"(addr));
}
#define CP_ASYNC16(dst, src) \
    asm volatile("cp.async.cg.shared.global [%0], [%1], 16;" :: "r"(dst), "l"(src))
#define CP_COMMIT() asm volatile("cp.async.commit_group;" ::: "memory")
#define CP_WAIT1()  asm volatile("cp.async.wait_group 1;" ::: "memory")
#define CP_WAIT0()  asm volatile("cp.async.wait_group 0;" ::: "memory")

__device__ __forceinline__ uint32_t pack_half2(float a, float b) {
    __half2 t = __floats2half2_rn(a, b);
    return *reinterpret_cast<uint32_t*>(&t);
}

// ---------------------------------------------------------------------------
// fp32 -> fp16 convert (optional scale)
// ---------------------------------------------------------------------------
__global__ void tohalf_kernel(const float* __restrict__ src,
                              __half* __restrict__ dst, int n, float scale) {
    int i = blockIdx.x * 256 + threadIdx.x;
    if (i >= n) return;
    dst[i] = __float2half(src[i] * scale);
}

// ---------------------------------------------------------------------------
// Transpose + convert: W[rows][Nd] fp32 -> WT[Nd][rows] fp16
// ---------------------------------------------------------------------------
__global__ void transpose_half_kernel(const float* __restrict__ W,
                                      __half* __restrict__ T,
                                      int Kd, int Nd) {
    __shared__ float t[32][33];
    int bx = blockIdx.x * 32;
    int by = blockIdx.y * 32;
    int tx = threadIdx.x, ty = threadIdx.y;
#pragma unroll
    for (int j = 0; j < 32; j += 8)
        t[ty + j][tx] = W[(size_t)(by + ty + j) * Nd + bx + tx];
    __syncthreads();
#pragma unroll
    for (int j = 0; j < 32; j += 8) {
        int n = bx + ty + j, k = by + tx;
        T[(size_t)n * Kd + k] = __float2half(t[tx][ty + j]);
    }
}

// ---------------------------------------------------------------------------
// Pipelined warp-MMA GEMM (fp16 single-pass): C = A[M,K] * B[N,K]^T
// Modes: 0 fp32 | 1 scale+fp16 | 2 RoPE+fp16 | 3 RoPE+fp32
// ---------------------------------------------------------------------------
#define SA  40
#define GTB (128 * SA * 2)          // 10240 bytes per tile
#define GEMM_SMEM (2 * 2 * GTB)     // 40960

__global__ __launch_bounds__(256) void gemm_mma_h(
    const __half* __restrict__ A, const __half* __restrict__ B,
    float* __restrict__ Cf, __half* __restrict__ Ch,
    const float* __restrict__ cosv, const float* __restrict__ sinv,
    int N, int Kd, int mode, float scale) {

    extern __shared__ char dsm[];
    uint32_t sb = smem_u32(dsm);

    const int tid  = threadIdx.x;
    const int lane = tid & 31;
    const int wid  = tid >> 5;
    const int wm   = (wid >> 1) * 32;
    const int wn   = (wid & 1) * 64;
    const int bm   = blockIdx.y * 128;
    const int bn   = blockIdx.x * 128;
    const int lrow = tid >> 2;
    const int lcb  = (tid & 3) * 16;
    const int grp  = lane >> 2;
    const int qd   = (lane & 3) * 2;

    const int arow_l = (lane & 7) + (((lane >> 3) & 1) << 3);
    const int acol_l = (lane >> 4) << 3;
    const int brow_l = (lane & 7) + ((lane >> 4) << 3);
    const int bcol_l = ((lane >> 3) & 1) << 3;

    const int nIter = Kd / 32;

    auto issue = [&](int it, int stage) {
        const size_t kb = (size_t)it * 64;
        uint32_t base = sb + stage * (2 * GTB);
#pragma unroll
        for (int rr = 0; rr < 2; rr++) {
            int row = lrow + rr * 64;
            uint32_t so = row * (SA * 2) + lcb;
            const char* g = (const char*)A + ((size_t)(bm + row) * Kd) * 2 + kb + lcb;
            CP_ASYNC16(base + so, g);
            g = (const char*)B + ((size_t)(bn + row) * Kd) * 2 + kb + lcb;
            CP_ASYNC16(base + GTB + so, g);
        }
        CP_COMMIT();
    };

    float acc[2][8][4];
#pragma unroll
    for (int i = 0; i < 2; i++)
#pragma unroll
        for (int j = 0; j < 8; j++)
#pragma unroll
            for (int k = 0; k < 4; k++) acc[i][j][k] = 0.f;

    issue(0, 0);
    if (nIter > 1) issue(1, 1);

    for (int it = 0; it < nIter; it++) {
        if (it + 1 < nIter) { CP_WAIT1(); } else { CP_WAIT0(); }
        __syncthreads();

        uint32_t buf = sb + (it & 1) * (2 * GTB);

#pragma unroll
        for (int ks = 0; ks < 2; ks++) {
            const int kc = ks * 16;
            uint32_t ah[2][4];
            uint32_t a0 = buf + ((wm + arow_l) * SA + kc + acol_l) * 2;
            ldsm_x4(ah[0], a0);
            ldsm_x4(ah[1], a0 + 16 * SA * 2);

            uint32_t bhf[16];
            uint32_t b0 = buf + GTB + ((wn + brow_l) * SA + kc + bcol_l) * 2;
#pragma unroll
            for (int p = 0; p < 4; p++)
                ldsm_x4(&bhf[p * 4], b0 + p * 16 * SA * 2);
#pragma unroll
            for (int mt = 0; mt < 2; mt++)
#pragma unroll
                for (int nt = 0; nt < 8; nt++)
                    mma16816(acc[mt][nt], ah[mt], &bhf[nt * 2]);
        }
        __syncthreads();
        if (it + 2 < nIter) issue(it + 2, it & 1);
    }

    // ---- epilogue ----
#pragma unroll
    for (int mt = 0; mt < 2; mt++) {
        int r = bm + wm + mt * 16 + grp;
#pragma unroll
        for (int nt = 0; nt < 8; nt++) {
            int c = bn + wn + nt * 8 + qd;
            float a0 = acc[mt][nt][0], a1 = acc[mt][nt][1];
            float a2 = acc[mt][nt][2], a3 = acc[mt][nt][3];
            size_t i0 = (size_t)r * N + c;
            size_t i1 = (size_t)(r + 8) * N + c;
            if (mode == 0) {
                *(float2*)&Cf[i0] = make_float2(a0, a1);
                *(float2*)&Cf[i1] = make_float2(a2, a3);
            } else if (mode == 1) {
                *(uint32_t*)&Ch[i0] = pack_half2(a0 * scale, a1 * scale);
                *(uint32_t*)&Ch[i1] = pack_half2(a2 * scale, a3 * scale);
            } else {
                int d2 = (c & 63) >> 1;
                float c0 = cosv[r * 32 + d2],       s0 = sinv[r * 32 + d2];
                float c1 = cosv[(r + 8) * 32 + d2], s1 = sinv[(r + 8) * 32 + d2];
                float o0 = a0 * c0 - a1 * s0, o1 = a0 * s0 + a1 * c0;
                float o2 = a2 * c1 - a3 * s1, o3 = a2 * s1 + a3 * c1;
                if (mode == 3) {
                    *(float2*)&Cf[i0] = make_float2(o0, o1);
                    *(float2*)&Cf[i1] = make_float2(o2, o3);
                } else {
                    *(uint32_t*)&Ch[i0] = pack_half2(o0, o1);
                    *(uint32_t*)&Ch[i1] = pack_half2(o2, o3);
                }
            }
        }
    }
}

// ---------------------------------------------------------------------------
// Pipelined MMA flash attention (fp16 single-pass), causal GQA.
// Grid (S/128, NH), 256 threads. Longest q-tiles scheduled first.
// ---------------------------------------------------------------------------
#define AST 72
#define ATB (64 * AST * 2)          // 9216
#define ATTN_SMEM (2 * 2 * ATB)     // 36864

__global__ __launch_bounds__(256) void attn_mma(
    const __half* __restrict__ Qh, const __half* __restrict__ Kh,
    const __half* __restrict__ VTh,
    __half* __restrict__ Yh) {

    extern __shared__ char dsm[];
    uint32_t sb = smem_u32(dsm);

    const int h    = blockIdx.y;
    const int kvh  = h >> 2;
    const int q0   = (gridDim.x - 1 - blockIdx.x) * 128;   // long tiles first
    const int tid  = threadIdx.x;
    const int lane = tid & 31;
    const int w    = tid >> 5;
    const int grp  = lane >> 2;
    const int qd   = (lane & 3) * 2;
    const int r0   = q0 + w * 16 + grp;

    const int brow_l = (lane & 7) + ((lane >> 4) << 3);
    const int bcol_l = ((lane >> 3) & 1) << 3;

    const int nChunks = (q0 >> 6) + 2;

    auto issueA = [&](int ci, int stage) {
        const int j0 = ci << 6;
        uint32_t base = sb + stage * (2 * ATB);
#pragma unroll
        for (int i = 0; i < 2; i++) {
            int c   = tid + i * 256;
            int row = c >> 3;
            int cb  = (c & 7) * 16;
            uint32_t so = row * (AST * 2) + cb;
            const char* g = (const char*)Kh + ((size_t)(j0 + row) * KVD + kvh * HD) * 2 + cb;
            CP_ASYNC16(base + so, g);
            g = (const char*)VTh + ((size_t)(kvh * HD + row) * S_LEN + j0) * 2 + cb;
            CP_ASYNC16(base + ATB + so, g);
        }
        CP_COMMIT();
    };

    // Q fragments, loaded once
    uint32_t qh[4][4];
#pragma unroll
    for (int jk = 0; jk < 4; jk++) {
        size_t c0 = (size_t)r0 * D_MODEL + h * HD + jk * 16 + qd;
        size_t c1 = (size_t)(r0 + 8) * D_MODEL + h * HD + jk * 16 + qd;
        qh[jk][0] = *(const uint32_t*)&Qh[c0];
        qh[jk][1] = *(const uint32_t*)&Qh[c1];
        qh[jk][2] = *(const uint32_t*)&Qh[c0 + 8];
        qh[jk][3] = *(const uint32_t*)&Qh[c1 + 8];
    }

    float o[8][4];
#pragma unroll
    for (int nt = 0; nt < 8; nt++)
#pragma unroll
        for (int i = 0; i < 4; i++) o[nt][i] = 0.f;

    float m0 = -1e30f, m1 = -1e30f, l0 = 0.f, l1 = 0.f;

    issueA(0, 0);
    if (nChunks > 1) issueA(1, 1);

    for (int ci = 0; ci < nChunks; ci++) {
        const int j0 = ci << 6;
        if (ci + 1 < nChunks) { CP_WAIT1(); } else { CP_WAIT0(); }
        __syncthreads();

        uint32_t buf = sb + (ci & 1) * (2 * ATB);

        // S = Q K^T
        float s[8][4];
#pragma unroll
        for (int nt = 0; nt < 8; nt++)
#pragma unroll
            for (int i = 0; i < 4; i++) s[nt][i] = 0.f;

#pragma unroll
        for (int jk = 0; jk < 4; jk++) {
            uint32_t bhf[16];
            uint32_t b0 = buf + (brow_l * AST + jk * 16 + bcol_l) * 2;
#pragma unroll
            for (int p = 0; p < 4; p++)
                ldsm_x4(&bhf[p * 4], b0 + p * 16 * AST * 2);
#pragma unroll
            for (int nt = 0; nt < 8; nt++)
                mma16816(s[nt], qh[jk], &bhf[nt * 2]);
        }

        if (ci >= nChunks - 2) {
#pragma unroll
            for (int nt = 0; nt < 8; nt++) {
                int col = j0 + nt * 8 + qd;
                if (col     > r0)     s[nt][0] = -1e30f;
                if (col + 1 > r0)     s[nt][1] = -1e30f;
                if (col     > r0 + 8) s[nt][2] = -1e30f;
                if (col + 1 > r0 + 8) s[nt][3] = -1e30f;
            }
        }

        float mx0 = -1e30f, mx1 = -1e30f;
#pragma unroll
        for (int nt = 0; nt < 8; nt++) {
            mx0 = fmaxf(mx0, fmaxf(s[nt][0], s[nt][1]));
            mx1 = fmaxf(mx1, fmaxf(s[nt][2], s[nt][3]));
        }
        mx0 = fmaxf(mx0, __shfl_xor_sync(0xffffffffu, mx0, 1));
        mx0 = fmaxf(mx0, __shfl_xor_sync(0xffffffffu, mx0, 2));
        mx1 = fmaxf(mx1, __shfl_xor_sync(0xffffffffu, mx1, 1));
        mx1 = fmaxf(mx1, __shfl_xor_sync(0xffffffffu, mx1, 2));

        float nm0 = fmaxf(m0, mx0), nm1 = fmaxf(m1, mx1);
        float corr0 = __expf(m0 - nm0), corr1 = __expf(m1 - nm1);

        uint32_t ph[4][4];
        float sum0 = 0.f, sum1 = 0.f;
#pragma unroll
        for (int nt = 0; nt < 8; nt++) {
            float p0 = __expf(s[nt][0] - nm0), p1 = __expf(s[nt][1] - nm0);
            float p2 = __expf(s[nt][2] - nm1), p3 = __expf(s[nt][3] - nm1);
            sum0 += p0 + p1;
            sum1 += p2 + p3;
            int jk2 = nt >> 1, hf = (nt & 1) * 2;
            ph[jk2][hf]     = pack_half2(p0, p1);
            ph[jk2][hf + 1] = pack_half2(p2, p3);
        }
        sum0 += __shfl_xor_sync(0xffffffffu, sum0, 1);
        sum0 += __shfl_xor_sync(0xffffffffu, sum0, 2);
        sum1 += __shfl_xor_sync(0xffffffffu, sum1, 1);
        sum1 += __shfl_xor_sync(0xffffffffu, sum1, 2);
        l0 = l0 * corr0 + sum0;
        l1 = l1 * corr1 + sum1;
        m0 = nm0; m1 = nm1;

#pragma unroll
        for (int nt = 0; nt < 8; nt++) {
            o[nt][0] *= corr0; o[nt][1] *= corr0;
            o[nt][2] *= corr1; o[nt][3] *= corr1;
        }

        // O += P V
#pragma unroll
        for (int jk = 0; jk < 4; jk++) {
            uint32_t bhf[16];
            uint32_t b0 = buf + ATB + (brow_l * AST + jk * 16 + bcol_l) * 2;
#pragma unroll
            for (int p = 0; p < 4; p++)
                ldsm_x4(&bhf[p * 4], b0 + p * 16 * AST * 2);
#pragma unroll
            for (int nt = 0; nt < 8; nt++)
                mma16816(o[nt], ph[jk], &bhf[nt * 2]);
        }

        __syncthreads();
        if (ci + 2 < nChunks) issueA(ci + 2, ci & 1);
    }

    float il0 = 1.f / l0, il1 = 1.f / l1;
#pragma unroll
    for (int nt = 0; nt < 8; nt++) {
        size_t c0 = (size_t)r0 * D_MODEL + h * HD + nt * 8 + qd;
        size_t c1 = (size_t)(r0 + 8) * D_MODEL + h * HD + nt * 8 + qd;
        *(uint32_t*)&Yh[c0] = pack_half2(o[nt][0] * il0, o[nt][1] * il0);
        *(uint32_t*)&Yh[c1] = pack_half2(o[nt][2] * il1, o[nt][3] * il1);
    }
}

// ---------------------------------------------------------------------------
extern "C" void kernel_launch(void* const* d_in, const int* in_sizes, int n_in,
                              void* d_out, int out_size) {
    const float* x    = (const float*)d_in[0];
    const float* tcos = (const float*)d_in[1];
    const float* tsin = (const float*)d_in[2];
    const float* wq   = (const float*)d_in[3];
    const float* wk   = (const float*)d_in[4];
    const float* wv   = (const float*)d_in[5];
    const float* wo   = (const float*)d_in[6];
    float* out = (float*)d_out;

    float* V;
    cudaGetSymbolAddress((void**)&V, g_V);

    __half *xh, *yh, *qh, *kh, *vth, *wqT, *wkT, *wvT, *woT;
    cudaGetSymbolAddress((void**)&xh,  g_xh);
    cudaGetSymbolAddress((void**)&yh,  g_yh);
    cudaGetSymbolAddress((void**)&qh,  g_qh);
    cudaGetSymbolAddress((void**)&kh,  g_kh);
    cudaGetSymbolAddress((void**)&vth, g_vth);
    cudaGetSymbolAddress((void**)&wqT, g_wqT);
    cudaGetSymbolAddress((void**)&wkT, g_wkT);
    cudaGetSymbolAddress((void**)&wvT, g_wvT);
    cudaGetSymbolAddress((void**)&woT, g_woT);

    cudaFuncSetAttribute(gemm_mma_h, cudaFuncAttributeMaxDynamicSharedMemorySize, GEMM_SMEM);
    cudaFuncSetAttribute(attn_mma,   cudaFuncAttributeMaxDynamicSharedMemorySize, ATTN_SMEM);

    const int nx = S_LEN * D_MODEL;

    // Convert x to fp16
    tohalf_kernel<<<(nx + 255) / 256, 256>>>(x, xh, nx, 1.0f);

    // Transpose+convert weights: W[K][N] -> WT[N][K] fp16
    transpose_half_kernel<<<dim3(D_MODEL / 32, D_MODEL / 32), dim3(32, 8)>>>(wq, wqT, D_MODEL, D_MODEL);
    transpose_half_kernel<<<dim3(KVD / 32,     D_MODEL / 32), dim3(32, 8)>>>(wk, wkT, D_MODEL, KVD);
    transpose_half_kernel<<<dim3(KVD / 32,     D_MODEL / 32), dim3(32, 8)>>>(wv, wvT, D_MODEL, KVD);
    transpose_half_kernel<<<dim3(D_MODEL / 32, D_MODEL / 32), dim3(32, 8)>>>(wo, woT, D_MODEL, D_MODEL);

    // Q projection: fused scale + fp16 epilogue
    gemm_mma_h<<<dim3(D_MODEL / 128, S_LEN / 128), 256, GEMM_SMEM>>>(
        xh, wqT, nullptr, qh, nullptr, nullptr, D_MODEL, D_MODEL, 1, 0.125f);
    // K projection: fused RoPE + fp16 epilogue
    gemm_mma_h<<<dim3(KVD / 128, S_LEN / 128), 256, GEMM_SMEM>>>(
        xh, wkT, nullptr, kh, tcos, tsin, KVD, D_MODEL, 2, 1.0f);
    // V projection: fused RoPE, fp32 out (then transposed)
    gemm_mma_h<<<dim3(KVD / 128, S_LEN / 128), 256, GEMM_SMEM>>>(
        xh, wvT, V, nullptr, tcos, tsin, KVD, D_MODEL, 3, 1.0f);

    // V transpose+convert for attention ([dim][seq] fp16)
    transpose_half_kernel<<<dim3(KVD / 32, S_LEN / 32), dim3(32, 8)>>>(V, vth, S_LEN, KVD);

    // MMA flash attention -> Yh (fp16)
    attn_mma<<<dim3(S_LEN / 128, NH), 256, ATTN_SMEM>>>(qh, kh, vth, yh);

    // Output projection (fp32 out)
    gemm_mma_h<<<dim3(D_MODEL / 128, S_LEN / 128), 256, GEMM_SMEM>>>(
        yh, woT, out, nullptr, nullptr, nullptr, D_MODEL, D_MODEL, 0, 1.0f);
}

// round 13
// speedup vs baseline: 2.7704x; 1.1550x over previous
#include <cuda_runtime.h>
#include <cuda_fp16.h>
#include <stdint.h>
#include <math.h>

#define S_LEN   2048
#define D_MODEL 2048
#define HD      64
#define NH      32
#define NKV     8
#define KVD     (NKV * HD)   // 512

// ---------------------------------------------------------------------------
// Scratch (__device__ globals; no allocation allowed)
// ---------------------------------------------------------------------------
__device__ __half g_xh[S_LEN * D_MODEL];
__device__ __half g_yh[S_LEN * D_MODEL];
__device__ __half g_qh[S_LEN * D_MODEL];
__device__ __half g_kh[S_LEN * KVD];
__device__ __half g_vh[S_LEN * KVD];
__device__ __half g_wq[D_MODEL * D_MODEL];   // [K][N] layouts (no transpose)
__device__ __half g_wo[D_MODEL * D_MODEL];
__device__ __half g_wk[D_MODEL * KVD];
__device__ __half g_wv[D_MODEL * KVD];

// ---------------------------------------------------------------------------
// PTX helpers
// ---------------------------------------------------------------------------
__device__ __forceinline__ uint32_t smem_u32(const void* p) {
    uint32_t a;
    asm("{ .reg .u64 t; cvta.to.shared.u64 t, %1; cvt.u32.u64 %0, t; }" : "=r"(a) : "l"(p));
    return a;
}
__device__ __forceinline__ void mma16816(float* c, const uint32_t* a, const uint32_t* b) {
    asm volatile(
        "mma.sync.aligned.m16n8k16.row.col.f32.f16.f16.f32 "
        "{%0,%1,%2,%3}, {%4,%5,%6,%7}, {%8,%9}, {%0,%1,%2,%3};"
        : "+f"(c[0]), "+f"(c[1]), "+f"(c[2]), "+f"(c[3])
        : "r"(a[0]), "r"(a[1]), "r"(a[2]), "r"(a[3]), "r"(b[0]), "r"(b[1]));
}
__device__ __forceinline__ void ldsm_x4(uint32_t* r, uint32_t addr) {
    asm volatile("ldmatrix.sync.aligned.m8n8.x4.shared.b16 {%0,%1,%2,%3}, [%4];"
        : "=r"(r[0]), "=r"(r[1]), "=r"(r[2]), "=r"(r[3]) : "r"(addr));
}
__device__ __forceinline__ void ldsm_x4_t(uint32_t* r, uint32_t addr) {
    asm volatile("ldmatrix.sync.aligned.m8n8.x4.trans.shared.b16 {%0,%1,%2,%3}, [%4];"
        : "=r"(r[0]), "=r"(r[1]), "=r"(r[2]), "=r"(r[3]) : "r"(addr));
}
#define CP_ASYNC16(dst, src) \
    asm volatile("cp.async.cg.shared.global [%0], [%1], 16;" :: "r"(dst), "l"(src))
#define CP_COMMIT() asm volatile("cp.async.commit_group;" ::: "memory")
#define CP_WAIT1()  asm volatile("cp.async.wait_group 1;" ::: "memory")
#define CP_WAIT0()  asm volatile("cp.async.wait_group 0;" ::: "memory")

__device__ __forceinline__ uint32_t pack_half2(float a, float b) {
    __half2 t = __floats2half2_rn(a, b);
    return *reinterpret_cast<uint32_t*>(&t);
}

// ---------------------------------------------------------------------------
// One fused fp32->fp16 conversion for x + all weights (same layout)
// ---------------------------------------------------------------------------
#define NX (S_LEN * D_MODEL)
#define NW (D_MODEL * D_MODEL)
#define NWK (D_MODEL * KVD)
#define NCONV (NX + 2 * NW + 2 * NWK)

__global__ void convert_all(const float* __restrict__ x,
                            const float* __restrict__ wq, const float* __restrict__ wk,
                            const float* __restrict__ wv, const float* __restrict__ wo,
                            __half* __restrict__ xh,
                            __half* __restrict__ wqh, __half* __restrict__ wkh,
                            __half* __restrict__ wvh, __half* __restrict__ woh) {
    int i = blockIdx.x * 256 + threadIdx.x;
    if (i < NX) { xh[i] = __float2half(x[i]); return; }
    i -= NX;
    if (i < NW) { wqh[i] = __float2half(wq[i]); return; }
    i -= NW;
    if (i < NWK) { wkh[i] = __float2half(wk[i]); return; }
    i -= NWK;
    if (i < NWK) { wvh[i] = __float2half(wv[i]); return; }
    i -= NWK;
    if (i < NW) { woh[i] = __float2half(wo[i]); }
}

// ---------------------------------------------------------------------------
// GEMM body: C[M,N] = A[M,K] * W[K,N]  (W K-major; B frags via ldmatrix.trans)
// 128x128 tile, 256 thr, 2-stage cp.async. Modes: 0 fp32 | 1 scale+fp16 | 2 RoPE+fp16
// ---------------------------------------------------------------------------
#define SA   40                      // A smem stride (halfs)
#define SBN  136                     // B smem stride (halfs)
#define GA   (128 * SA * 2)          // 10240
#define GB   (32 * SBN * 2)          // 8704
#define GSTG (GA + GB)               // 18944
#define GEMM_SMEM (2 * GSTG)         // 37888

__device__ __forceinline__ void gemm_body(
    const __half* __restrict__ A, const __half* __restrict__ W,
    float* __restrict__ Cf, __half* __restrict__ Ch,
    const float* __restrict__ cosv, const float* __restrict__ sinv,
    int N, int Kd, int mode, float scale, int bm, int bn, char* dsm) {

    uint32_t sb = smem_u32(dsm);

    const int tid  = threadIdx.x;
    const int lane = tid & 31;
    const int wid  = tid >> 5;
    const int wm   = (wid >> 1) * 32;
    const int wn   = (wid & 1) * 64;
    const int lrow = tid >> 2;
    const int lcb  = (tid & 3) * 16;
    const int grp  = lane >> 2;
    const int qd   = (lane & 3) * 2;

    const int arow_l  = (lane & 7) + (((lane >> 3) & 1) << 3);
    const int acol_l  = (lane >> 4) << 3;
    const int btrow_l = (lane & 7) + (((lane >> 3) & 1) << 3);   // k-row
    const int btcol_l = ((lane >> 4) & 1) << 3;                  // n-col (halfs)

    const int nIter = Kd / 32;

    auto issue = [&](int it, int stage) {
        uint32_t base = sb + stage * GSTG;
        const size_t kb = (size_t)it * 64;   // A byte offset along K
#pragma unroll
        for (int rr = 0; rr < 2; rr++) {
            int row = lrow + rr * 64;
            CP_ASYNC16(base + row * (SA * 2) + lcb,
                       (const char*)A + ((size_t)(bm + row) * Kd) * 2 + kb + lcb);
        }
#pragma unroll
        for (int i = 0; i < 2; i++) {
            int c = tid + i * 256;           // 0..511
            int krow = c >> 4;               // 0..31
            int cb = (c & 15) * 16;          // 0..240
            CP_ASYNC16(base + GA + krow * (SBN * 2) + cb,
                       (const char*)W + ((size_t)(it * 32 + krow) * N + bn) * 2 + cb);
        }
        CP_COMMIT();
    };

    float acc[2][8][4];
#pragma unroll
    for (int i = 0; i < 2; i++)
#pragma unroll
        for (int j = 0; j < 8; j++)
#pragma unroll
            for (int k = 0; k < 4; k++) acc[i][j][k] = 0.f;

    issue(0, 0);
    issue(1, 1);

    for (int it = 0; it < nIter; it++) {
        if (it + 1 < nIter) { CP_WAIT1(); } else { CP_WAIT0(); }
        __syncthreads();

        uint32_t bufA = sb + (it & 1) * GSTG;
        uint32_t bufB = bufA + GA;

#pragma unroll
        for (int ks = 0; ks < 2; ks++) {
            const int kc = ks * 16;
            uint32_t ah[2][4];
            uint32_t a0 = bufA + ((wm + arow_l) * SA + kc + acol_l) * 2;
            ldsm_x4(ah[0], a0);
            ldsm_x4(ah[1], a0 + 16 * SA * 2);

            uint32_t bhf[16];
#pragma unroll
            for (int p = 0; p < 4; p++)
                ldsm_x4_t(&bhf[p * 4],
                          bufB + (kc + btrow_l) * (SBN * 2) + (wn + p * 16 + btcol_l) * 2);
#pragma unroll
            for (int mt = 0; mt < 2; mt++)
#pragma unroll
                for (int nt = 0; nt < 8; nt++)
                    mma16816(acc[mt][nt], ah[mt], &bhf[nt * 2]);
        }
        __syncthreads();
        if (it + 2 < nIter) issue(it + 2, it & 1);
    }

    // ---- epilogue ----
#pragma unroll
    for (int mt = 0; mt < 2; mt++) {
        int r = bm + wm + mt * 16 + grp;
#pragma unroll
        for (int nt = 0; nt < 8; nt++) {
            int c = bn + wn + nt * 8 + qd;
            float a0 = acc[mt][nt][0], a1 = acc[mt][nt][1];
            float a2 = acc[mt][nt][2], a3 = acc[mt][nt][3];
            size_t i0 = (size_t)r * N + c;
            size_t i1 = (size_t)(r + 8) * N + c;
            if (mode == 0) {
                *(float2*)&Cf[i0] = make_float2(a0, a1);
                *(float2*)&Cf[i1] = make_float2(a2, a3);
            } else if (mode == 1) {
                *(uint32_t*)&Ch[i0] = pack_half2(a0 * scale, a1 * scale);
                *(uint32_t*)&Ch[i1] = pack_half2(a2 * scale, a3 * scale);
            } else {
                int d2 = (c & 63) >> 1;
                float c0 = cosv[r * 32 + d2],       s0 = sinv[r * 32 + d2];
                float c1 = cosv[(r + 8) * 32 + d2], s1 = sinv[(r + 8) * 32 + d2];
                *(uint32_t*)&Ch[i0] = pack_half2(a0 * c0 - a1 * s0, a0 * s0 + a1 * c0);
                *(uint32_t*)&Ch[i1] = pack_half2(a2 * c1 - a3 * s1, a2 * s1 + a3 * c1);
            }
        }
    }
}

// Merged Q/K/V projections: 256 + 64 + 64 = 384 blocks in one launch.
__global__ __launch_bounds__(256) void qkv_gemm(
    const __half* __restrict__ xh,
    const __half* __restrict__ wq, const __half* __restrict__ wk, const __half* __restrict__ wv,
    __half* __restrict__ qh, __half* __restrict__ kh, __half* __restrict__ vh,
    const float* __restrict__ cosv, const float* __restrict__ sinv) {
    extern __shared__ char dsm[];
    int id = blockIdx.x;
    if (id < 256) {
        gemm_body(xh, wq, nullptr, qh, nullptr, nullptr,
                  D_MODEL, D_MODEL, 1, 0.125f, (id >> 4) * 128, (id & 15) * 128, dsm);
    } else if (id < 320) {
        int t = id - 256;
        gemm_body(xh, wk, nullptr, kh, cosv, sinv,
                  KVD, D_MODEL, 2, 1.0f, (t >> 2) * 128, (t & 3) * 128, dsm);
    } else {
        int t = id - 320;
        gemm_body(xh, wv, nullptr, vh, cosv, sinv,
                  KVD, D_MODEL, 2, 1.0f, (t >> 2) * 128, (t & 3) * 128, dsm);
    }
}

__global__ __launch_bounds__(256) void wo_gemm(
    const __half* __restrict__ yh, const __half* __restrict__ wo, float* __restrict__ out) {
    extern __shared__ char dsm[];
    gemm_body(yh, wo, out, nullptr, nullptr, nullptr,
              D_MODEL, D_MODEL, 0, 1.0f, blockIdx.y * 128, blockIdx.x * 128, dsm);
}

// ---------------------------------------------------------------------------
// Pipelined MMA flash attention (fp16), causal GQA. V in natural [seq][dim]
// layout; PV B-fragments via ldmatrix.trans. Grid (S/128, NH), 256 threads.
// ---------------------------------------------------------------------------
#define AST 72
#define ATB (64 * AST * 2)          // 9216
#define ATTN_SMEM (2 * 2 * ATB)     // 36864

__global__ __launch_bounds__(256) void attn_mma(
    const __half* __restrict__ Qh, const __half* __restrict__ Kh,
    const __half* __restrict__ Vh, __half* __restrict__ Yh) {

    extern __shared__ char dsm[];
    uint32_t sb = smem_u32(dsm);

    const int h    = blockIdx.y;
    const int kvh  = h >> 2;
    const int q0   = (gridDim.x - 1 - blockIdx.x) * 128;   // long tiles first
    const int tid  = threadIdx.x;
    const int lane = tid & 31;
    const int w    = tid >> 5;
    const int grp  = lane >> 2;
    const int qd   = (lane & 3) * 2;
    const int r0   = q0 + w * 16 + grp;

    const int brow_l  = (lane & 7) + ((lane >> 4) << 3);          // K (non-trans)
    const int bcol_l  = ((lane >> 3) & 1) << 3;
    const int btrow_l = (lane & 7) + (((lane >> 3) & 1) << 3);    // V (trans)
    const int btcol_l = ((lane >> 4) & 1) << 3;

    const int nChunks = (q0 >> 6) + 2;

    auto issueA = [&](int ci, int stage) {
        const int j0 = ci << 6;
        uint32_t base = sb + stage * (2 * ATB);
#pragma unroll
        for (int i = 0; i < 2; i++) {
            int c   = tid + i * 256;
            int row = c >> 3;
            int cb  = (c & 7) * 16;
            uint32_t so = row * (AST * 2) + cb;
            size_t go = ((size_t)(j0 + row) * KVD + kvh * HD) * 2 + cb;
            CP_ASYNC16(base + so,       (const char*)Kh + go);
            CP_ASYNC16(base + ATB + so, (const char*)Vh + go);
        }
        CP_COMMIT();
    };

    // Q fragments, loaded once
    uint32_t qh[4][4];
#pragma unroll
    for (int jk = 0; jk < 4; jk++) {
        size_t c0 = (size_t)r0 * D_MODEL + h * HD + jk * 16 + qd;
        size_t c1 = (size_t)(r0 + 8) * D_MODEL + h * HD + jk * 16 + qd;
        qh[jk][0] = *(const uint32_t*)&Qh[c0];
        qh[jk][1] = *(const uint32_t*)&Qh[c1];
        qh[jk][2] = *(const uint32_t*)&Qh[c0 + 8];
        qh[jk][3] = *(const uint32_t*)&Qh[c1 + 8];
    }

    float o[8][4];
#pragma unroll
    for (int nt = 0; nt < 8; nt++)
#pragma unroll
        for (int i = 0; i < 4; i++) o[nt][i] = 0.f;

    float m0 = -1e30f, m1 = -1e30f, l0 = 0.f, l1 = 0.f;

    issueA(0, 0);
    if (nChunks > 1) issueA(1, 1);

    for (int ci = 0; ci < nChunks; ci++) {
        const int j0 = ci << 6;
        if (ci + 1 < nChunks) { CP_WAIT1(); } else { CP_WAIT0(); }
        __syncthreads();

        uint32_t bufK = sb + (ci & 1) * (2 * ATB);
        uint32_t bufV = bufK + ATB;

        // S = Q K^T
        float s[8][4];
#pragma unroll
        for (int nt = 0; nt < 8; nt++)
#pragma unroll
            for (int i = 0; i < 4; i++) s[nt][i] = 0.f;

#pragma unroll
        for (int jk = 0; jk < 4; jk++) {
            uint32_t bhf[16];
            uint32_t b0 = bufK + (brow_l * AST + jk * 16 + bcol_l) * 2;
#pragma unroll
            for (int p = 0; p < 4; p++)
                ldsm_x4(&bhf[p * 4], b0 + p * 16 * AST * 2);
#pragma unroll
            for (int nt = 0; nt < 8; nt++)
                mma16816(s[nt], qh[jk], &bhf[nt * 2]);
        }

        if (ci >= nChunks - 2) {
#pragma unroll
            for (int nt = 0; nt < 8; nt++) {
                int col = j0 + nt * 8 + qd;
                if (col     > r0)     s[nt][0] = -1e30f;
                if (col + 1 > r0)     s[nt][1] = -1e30f;
                if (col     > r0 + 8) s[nt][2] = -1e30f;
                if (col + 1 > r0 + 8) s[nt][3] = -1e30f;
            }
        }

        float mx0 = -1e30f, mx1 = -1e30f;
#pragma unroll
        for (int nt = 0; nt < 8; nt++) {
            mx0 = fmaxf(mx0, fmaxf(s[nt][0], s[nt][1]));
            mx1 = fmaxf(mx1, fmaxf(s[nt][2], s[nt][3]));
        }
        mx0 = fmaxf(mx0, __shfl_xor_sync(0xffffffffu, mx0, 1));
        mx0 = fmaxf(mx0, __shfl_xor_sync(0xffffffffu, mx0, 2));
        mx1 = fmaxf(mx1, __shfl_xor_sync(0xffffffffu, mx1, 1));
        mx1 = fmaxf(mx1, __shfl_xor_sync(0xffffffffu, mx1, 2));

        float nm0 = fmaxf(m0, mx0), nm1 = fmaxf(m1, mx1);
        float corr0 = __expf(m0 - nm0), corr1 = __expf(m1 - nm1);

        uint32_t ph[4][4];
        float sum0 = 0.f, sum1 = 0.f;
#pragma unroll
        for (int nt = 0; nt < 8; nt++) {
            float p0 = __expf(s[nt][0] - nm0), p1 = __expf(s[nt][1] - nm0);
            float p2 = __expf(s[nt][2] - nm1), p3 = __expf(s[nt][3] - nm1);
            sum0 += p0 + p1;
            sum1 += p2 + p3;
            int jk2 = nt >> 1, hf = (nt & 1) * 2;
            ph[jk2][hf]     = pack_half2(p0, p1);
            ph[jk2][hf + 1] = pack_half2(p2, p3);
        }
        sum0 += __shfl_xor_sync(0xffffffffu, sum0, 1);
        sum0 += __shfl_xor_sync(0xffffffffu, sum0, 2);
        sum1 += __shfl_xor_sync(0xffffffffu, sum1, 1);
        sum1 += __shfl_xor_sync(0xffffffffu, sum1, 2);
        l0 = l0 * corr0 + sum0;
        l1 = l1 * corr1 + sum1;
        m0 = nm0; m1 = nm1;

#pragma unroll
        for (int nt = 0; nt < 8; nt++) {
            o[nt][0] *= corr0; o[nt][1] *= corr0;
            o[nt][2] *= corr1; o[nt][3] *= corr1;
        }

        // O += P V   (V [seq][dim] -> trans ldmatrix gives V^T fragments)
#pragma unroll
        for (int jk = 0; jk < 4; jk++) {
            uint32_t bhf[16];
#pragma unroll
            for (int p = 0; p < 4; p++)
                ldsm_x4_t(&bhf[p * 4],
                          bufV + (jk * 16 + btrow_l) * (AST * 2) + (p * 16 + btcol_l) * 2);
#pragma unroll
            for (int nt = 0; nt < 8; nt++)
                mma16816(o[nt], ph[jk], &bhf[nt * 2]);
        }

        __syncthreads();
        if (ci + 2 < nChunks) issueA(ci + 2, ci & 1);
    }

    float il0 = 1.f / l0, il1 = 1.f / l1;
#pragma unroll
    for (int nt = 0; nt < 8; nt++) {
        size_t c0 = (size_t)r0 * D_MODEL + h * HD + nt * 8 + qd;
        size_t c1 = (size_t)(r0 + 8) * D_MODEL + h * HD + nt * 8 + qd;
        *(uint32_t*)&Yh[c0] = pack_half2(o[nt][0] * il0, o[nt][1] * il0);
        *(uint32_t*)&Yh[c1] = pack_half2(o[nt][2] * il1, o[nt][3] * il1);
    }
}

// ---------------------------------------------------------------------------
extern "C" void kernel_launch(void* const* d_in, const int* in_sizes, int n_in,
                              void* d_out, int out_size) {
    const float* x    = (const float*)d_in[0];
    const float* tcos = (const float*)d_in[1];
    const float* tsin = (const float*)d_in[2];
    const float* wq   = (const float*)d_in[3];
    const float* wk   = (const float*)d_in[4];
    const float* wv   = (const float*)d_in[5];
    const float* wo   = (const float*)d_in[6];
    float* out = (float*)d_out;

    __half *xh, *yh, *qh, *kh, *vh, *wqh, *wkh, *wvh, *woh;
    cudaGetSymbolAddress((void**)&xh,  g_xh);
    cudaGetSymbolAddress((void**)&yh,  g_yh);
    cudaGetSymbolAddress((void**)&qh,  g_qh);
    cudaGetSymbolAddress((void**)&kh,  g_kh);
    cudaGetSymbolAddress((void**)&vh,  g_vh);
    cudaGetSymbolAddress((void**)&wqh, g_wq);
    cudaGetSymbolAddress((void**)&wkh, g_wk);
    cudaGetSymbolAddress((void**)&wvh, g_wv);
    cudaGetSymbolAddress((void**)&woh, g_wo);

    cudaFuncSetAttribute(qkv_gemm, cudaFuncAttributeMaxDynamicSharedMemorySize, GEMM_SMEM);
    cudaFuncSetAttribute(wo_gemm,  cudaFuncAttributeMaxDynamicSharedMemorySize, GEMM_SMEM);
    cudaFuncSetAttribute(attn_mma, cudaFuncAttributeMaxDynamicSharedMemorySize, ATTN_SMEM);

    // 1. Convert x + all weights to fp16 (one launch)
    convert_all<<<(NCONV + 255) / 256, 256>>>(x, wq, wk, wv, wo, xh, wqh, wkh, wvh, woh);

    // 2. Fused Q/K/V projections (Q: scale; K,V: RoPE) in one launch
    qkv_gemm<<<384, 256, GEMM_SMEM>>>(xh, wqh, wkh, wvh, qh, kh, vh, tcos, tsin);

    // 3. MMA flash attention -> Yh (fp16)
    attn_mma<<<dim3(S_LEN / 128, NH), 256, ATTN_SMEM>>>(qh, kh, vh, yh);

    // 4. Output projection (fp32 out)
    wo_gemm<<<dim3(D_MODEL / 128, S_LEN / 128), 256, GEMM_SMEM>>>(yh, woh, out);
}